// round 15
// baseline (speedup 1.0000x reference)
#include <cuda_runtime.h>
#include <cuda_bf16.h>
#include <math.h>
#include <stdint.h>

typedef unsigned long long u64;

// Problem dims
#define B_ 64
#define T_ 512
#define D_ 512
#define U_ 1024
#define N4U 4096        // 4*U
#define BT_ (B_ * T_)   // 32768

#define NB2 128         // persistent blocks (1 per SM)

// mma.sync m16n8k16 bf16 (base PTX, works on compute_103) --------------------
#define MMA16816(c, a, b) \
    asm volatile("mma.sync.aligned.m16n8k16.row.col.f32.bf16.bf16.f32 " \
        "{%0,%1,%2,%3}, {%4,%5,%6,%7}, {%8,%9}, {%0,%1,%2,%3};" \
        : "+f"((c)[0]), "+f"((c)[1]), "+f"((c)[2]), "+f"((c)[3]) \
        : "r"((a)[0]), "r"((a)[1]), "r"((a)[2]), "r"((a)[3]), \
          "r"((b)[0]), "r"((b)[1]))

__device__ __forceinline__ float fsigmoid(float x) {
    return __fdividef(1.f, 1.f + __expf(-x));
}
__device__ __forceinline__ float ftanh(float x) {
    float e = __expf(2.f * x);
    return 1.f - __fdividef(2.f, e + 1.f);
}

// ---------------- scratch (device globals) ----------------------------------
// h in MMA-fragment-major order (recurrence)
__device__ __nv_bfloat16 g_hhiP[2][B_ * U_];
__device__ __nv_bfloat16 g_hloP[2][B_ * U_];
__device__ unsigned g_bar2[T_];                       // per-step barrier counters
// x fragment-major per timestep: [t][k16=32][tile_b=4][lane=32][8 bf16]
__device__ __nv_bfloat16 g_xFhi[(size_t)BT_ * D_];
__device__ __nv_bfloat16 g_xFlo[(size_t)BT_ * D_];
// Wx (x-proj W^T) fragment-major: [n8=512][k16=32][lane=32][8 = bh0 bh1 bl0 bl1]
__device__ __nv_bfloat16 g_wF[(size_t)N4U * D_ * 2];

// ---------------- init -------------------------------------------------------
__global__ void lstm_init() {
    int i = blockIdx.x * blockDim.x + threadIdx.x;
    if (i < B_ * U_) {
        g_hhiP[0][i] = __float2bfloat16(0.f);
        g_hloP[0][i] = __float2bfloat16(0.f);
    }
    if (i < T_) g_bar2[i] = 0u;
}

// ---------------- split-precision converters (fragment-major output) ----------
__global__ void conv_x(const float* __restrict__ x) {
    size_t i = (size_t)blockIdx.x * blockDim.x + threadIdx.x;
    if (i >= (size_t)BT_ * D_) return;
    int bt = (int)(i >> 9);       // b*T + t  (x is [B][T][D] row-major)
    int k = (int)(i & 511);
    int b = bt >> 9;              // T = 512
    int t = bt & 511;
    float v = x[i];
    __nv_bfloat16 hi = __float2bfloat16(v);
    __nv_bfloat16 lo = __float2bfloat16(v - __bfloat162float(hi));
    int tile_b = b >> 4, rr = b & 15;
    int k16 = k >> 4, kk = k & 15;
    int lane = (rr & 7) * 4 + ((kk >> 1) & 3);
    int reg = ((rr >> 3) & 1) | ((kk >> 3) << 1);
    size_t base = (((size_t)t * 32 + k16) * 4 + tile_b) * 256 + lane * 8 + reg * 2 + (kk & 1);
    g_xFhi[base] = hi;
    g_xFlo[base] = lo;
}
__global__ void conv_w(const float* __restrict__ W) {
    size_t i = (size_t)blockIdx.x * blockDim.x + threadIdx.x;  // over n*512+k
    if (i >= (size_t)N4U * D_) return;
    int n = (int)(i >> 9);
    int k = (int)(i & 511);
    float v = W[(size_t)k * N4U + n];
    __nv_bfloat16 hi = __float2bfloat16(v);
    __nv_bfloat16 lo = __float2bfloat16(v - __bfloat162float(hi));
    int n8 = n >> 3, k16 = k >> 4;
    int lane = (n & 7) * 4 + ((k >> 1) & 3);
    int reg = (k >> 3) & 1;
    int e = k & 1;
    size_t base = (((size_t)n8 * 32 + k16) * 32 + lane) * 8;
    g_wF[base + reg * 2 + e] = hi;
    g_wF[base + 4 + reg * 2 + e] = lo;
}

// ---------------- grid-wide barrier (counter per step) --------------------------
__device__ __forceinline__ void gridbar2(int t) {
    __syncthreads();
    if (threadIdx.x == 0) {
        __threadfence();
        atomicAdd(&g_bar2[t], 1u);
        while (((volatile unsigned*)g_bar2)[t] < (unsigned)NB2) __nanosleep(32);
    }
    __syncthreads();
    __threadfence();
}

// ---------------- persistent fused LSTM: z = [x(t), h(t)] @ [Wx; Wrec] ---------
// 128 blocks x 512 thr. Block owns 8 units (32 z-cols).
// Warps: wm = wid&3 (batch m16-tile), kq = wid>>2 (K-quarter).
// Pre-barrier: x-part (K=512, kq slice 128 = 8 k16) — no h dependency, overlaps
// barrier wait. Post-barrier: h-part (K=1024, kq slice 256 = 16 k16, W in smem).
__global__ __launch_bounds__(512)
void lstm_persist_mma(const float* __restrict__ W, float* __restrict__ out) {
    extern __shared__ char sm2[];
    __nv_bfloat16* Wp = (__nv_bfloat16*)sm2;         // 65536 bf16 = 128 KB (Wrec)
    float4* Zs4 = (float4*)(Wp + 65536);             // [4][576] float4 (b*9+u pad)

    const int tid = threadIdx.x;
    const int wid = tid >> 5;
    const int lane = tid & 31;
    const int wm = wid & 3;
    const int kq = wid >> 2;          // 0..3
    const int bx = blockIdx.x;
    const int u0 = bx * 8;
    const int lq = lane >> 2;
    const int lr = (lane & 3) << 1;

    // ---- load + split + permute Wrec tile into smem (once): 32 cols x 1024 k ----
    for (int l = 0; l < 64; l++) {
        int idx = tid + l * 512;
        int cc = idx & 31;            // j = cc>>3 (gate), n = cc&7
        int k = idx >> 5;             // 0..1023
        int col = ((cc >> 3) << 10) + u0 + (cc & 7);
        float v = W[(size_t)k * N4U + col];
        __nv_bfloat16 hi = __float2bfloat16(v);
        __nv_bfloat16 lo = __float2bfloat16(v - __bfloat162float(hi));
        int kqi = k >> 8, si = (k >> 4) & 15, kk = k & 15;
        int j = cc >> 3, n = cc & 7;
        int ln = n * 4 + ((kk >> 1) & 3);
        int reg = kk >> 3, elem = kk & 1;
        int base = (((kqi * 16 + si) * 4 + j) * 32 + ln) * 8;
        Wp[base + reg * 2 + elem] = hi;
        Wp[base + 4 + reg * 2 + elem] = lo;
    }

    // ---- finisher cell: 1 per thread; precompute permuted h write addr ----
    const int fb = tid >> 3;          // batch 0..63
    const int fu = tid & 7;           // unit within tile
    const int ug = u0 + fu;           // global unit = h column
    float c_reg = 0.f;
    int paddr;
    {
        int r = fb & 15, wmw = fb >> 4;
        int kqw = ug >> 8, sw = (ug >> 4) & 15, cw = ug & 15;
        int lnw = (r & 7) * 4 + ((cw >> 1) & 3);
        int regw = (r >> 3) | ((cw >> 3) << 1);
        paddr = (((kqw * 16 + sw) * 4 + wmw) * 256) + lnw * 8 + regw * 2 + (cw & 1);
    }

    float4* Zsl4 = Zs4 + kq * 576;
    const int ra = wm * 16 + lq;
    const int tbase = (kq * 16) * 4 + wm;   // h tile id at s=0
    // B-frag gmem bases for the 4 gates (x-part)
    const size_t wfb0 = (((size_t)(0 * 128 + bx) * 32 + kq * 8) * 32 + lane) * 8;
    const size_t wfb1 = (((size_t)(1 * 128 + bx) * 32 + kq * 8) * 32 + lane) * 8;
    const size_t wfb2 = (((size_t)(2 * 128 + bx) * 32 + kq * 8) * 32 + lane) * 8;
    const size_t wfb3 = (((size_t)(3 * 128 + bx) * 32 + kq * 8) * 32 + lane) * 8;

    for (int t = 0; t < T_; t++) {
        float acc[4][4];
        #pragma unroll
        for (int j = 0; j < 4; j++)
            #pragma unroll
            for (int q = 0; q < 4; q++) acc[j][q] = 0.f;

        // ======== PRE-BARRIER: x-projection part (K slice 128 = 8 k16) ========
        {
            const size_t xoff = (((size_t)t * 32 + kq * 8) * 4 + wm) * 256 + lane * 8;
            #pragma unroll
            for (int s = 0; s < 8; s++) {
                uint4 Ah = *(const uint4*)(g_xFhi + xoff + (size_t)s * 1024);
                uint4 Al = *(const uint4*)(g_xFlo + xoff + (size_t)s * 1024);
                const uint32_t* ahi = (const uint32_t*)&Ah;
                const uint32_t* alo = (const uint32_t*)&Al;
                uint4 wv0 = *(const uint4*)(g_wF + wfb0 + (size_t)s * 256);
                uint4 wv1 = *(const uint4*)(g_wF + wfb1 + (size_t)s * 256);
                uint4 wv2 = *(const uint4*)(g_wF + wfb2 + (size_t)s * 256);
                uint4 wv3 = *(const uint4*)(g_wF + wfb3 + (size_t)s * 256);
                uint4 wvs[4] = {wv0, wv1, wv2, wv3};
                #pragma unroll
                for (int j = 0; j < 4; j++) {
                    uint32_t bh[2] = {wvs[j].x, wvs[j].y};
                    uint32_t bl[2] = {wvs[j].z, wvs[j].w};
                    MMA16816(acc[j], ahi, bh);
                    MMA16816(acc[j], ahi, bl);
                    MMA16816(acc[j], alo, bh);
                }
            }
        }

        gridbar2(t);   // all h[t&1] writes visible; covers Wp smem load at t=0

        // ======== POST-BARRIER: recurrent part (K slice 256 = 16 k16) ========
        const __nv_bfloat16* __restrict__ hh = g_hhiP[t & 1];
        const __nv_bfloat16* __restrict__ hl = g_hloP[t & 1];
        {
            const int off0 = tbase * 256 + lane * 8;
            uint4 Ah = *(const uint4*)(hh + off0);
            uint4 Al = *(const uint4*)(hl + off0);
            #pragma unroll
            for (int s = 0; s < 16; s++) {
                uint4 Ah_n, Al_n;
                if (s < 15) {
                    const int offn = (tbase + (s + 1) * 4) * 256 + lane * 8;
                    Ah_n = *(const uint4*)(hh + offn);
                    Al_n = *(const uint4*)(hl + offn);
                }
                const uint32_t* ahi = (const uint32_t*)&Ah;
                const uint32_t* alo = (const uint32_t*)&Al;
                #pragma unroll
                for (int j = 0; j < 4; j++) {
                    uint4 wv = *(const uint4*)(Wp + (((kq * 16 + s) * 4 + j) * 32 + lane) * 8);
                    uint32_t bh[2] = {wv.x, wv.y};
                    uint32_t bl[2] = {wv.z, wv.w};
                    MMA16816(acc[j], ahi, bh);
                    MMA16816(acc[j], ahi, bl);
                    MMA16816(acc[j], alo, bh);
                }
                if (s < 15) { Ah = Ah_n; Al = Al_n; }
            }
        }

        // ---- Zs slice write: gate-contiguous float4 per (b,u) ----
        Zsl4[ra * 9 + lr]           = make_float4(acc[0][0], acc[1][0], acc[2][0], acc[3][0]);
        Zsl4[ra * 9 + lr + 1]       = make_float4(acc[0][1], acc[1][1], acc[2][1], acc[3][1]);
        Zsl4[(ra + 8) * 9 + lr]     = make_float4(acc[0][2], acc[1][2], acc[2][2], acc[3][2]);
        Zsl4[(ra + 8) * 9 + lr + 1] = make_float4(acc[0][3], acc[1][3], acc[2][3], acc[3][3]);
        __syncthreads();

        // ---- finisher: 1 cell per thread; fixed-order kq sum (4 LDS.128) ----
        __nv_bfloat16* __restrict__ nhh = g_hhiP[(t + 1) & 1];
        __nv_bfloat16* __restrict__ nhl = g_hloP[(t + 1) & 1];
        {
            float z0 = 0.f, z1 = 0.f, z2 = 0.f, z3 = 0.f;
            #pragma unroll
            for (int p = 0; p < 4; p++) {
                float4 zp = Zs4[p * 576 + fb * 9 + fu];
                z0 += zp.x; z1 += zp.y; z2 += zp.z; z3 += zp.w;
            }
            float iv = fsigmoid(z0);
            float fv = fsigmoid(z1);
            float gv = ftanh(z2);
            float ov = fsigmoid(z3);
            c_reg = fv * c_reg + iv * gv;
            float hv = ov * ftanh(c_reg);
            __nv_bfloat16 hi = __float2bfloat16(hv);
            nhh[paddr] = hi;
            nhl[paddr] = __float2bfloat16(hv - __bfloat162float(hi));
            if (t == T_ - 1) out[fb * U_ + ug] = hv;
        }
        // next iteration's gridbar2 orders Zs reuse and h visibility
    }
}

// ---------------- launch --------------------------------------------------------
extern "C" void kernel_launch(void* const* d_in, const int* in_sizes, int n_in,
                              void* d_out, int out_size) {
    const float* x    = (const float*)d_in[0];
    const float* kern = (const float*)d_in[1];
    const float* rec  = (const float*)d_in[2];
    float* out = (float*)d_out;

    static int attr_done = 0;
    const size_t smem2 = (size_t)65536 * sizeof(__nv_bfloat16)
                       + (size_t)(4 * 576) * sizeof(float4);   // 128K + 36K = ~165 KB
    if (!attr_done) {
        cudaFuncSetAttribute(lstm_persist_mma,
                             cudaFuncAttributeMaxDynamicSharedMemorySize, (int)smem2);
        cudaFuncSetAttribute(lstm_persist_mma,
                             cudaFuncAttributePreferredSharedMemoryCarveout, 100);
        attr_done = 1;
    }

    lstm_init<<<(B_ * U_ + 255) / 256, 256>>>();

    conv_x<<<(int)(((size_t)BT_ * D_ + 255) / 256), 256>>>(x);
    conv_w<<<(int)(((size_t)N4U * D_ + 255) / 256), 256>>>(kern);

    lstm_persist_mma<<<NB2, 512, smem2>>>(rec, out);
}

// round 16
// speedup vs baseline: 1.0857x; 1.0857x over previous
#include <cuda_runtime.h>
#include <cuda_bf16.h>
#include <math.h>
#include <stdint.h>

typedef unsigned long long u64;

// Problem dims
#define B_ 64
#define T_ 512
#define D_ 512
#define U_ 1024
#define N4U 4096        // 4*U
#define BT_ (B_ * T_)   // 32768

#define NB2 128         // persistent blocks (1 per SM)

// mma.sync m16n8k16 bf16 (base PTX, works on compute_103) --------------------
#define MMA16816(c, a, b) \
    asm volatile("mma.sync.aligned.m16n8k16.row.col.f32.bf16.bf16.f32 " \
        "{%0,%1,%2,%3}, {%4,%5,%6,%7}, {%8,%9}, {%0,%1,%2,%3};" \
        : "+f"((c)[0]), "+f"((c)[1]), "+f"((c)[2]), "+f"((c)[3]) \
        : "r"((a)[0]), "r"((a)[1]), "r"((a)[2]), "r"((a)[3]), \
          "r"((b)[0]), "r"((b)[1]))

__device__ __forceinline__ float fsigmoid(float x) {
    return __fdividef(1.f, 1.f + __expf(-x));
}
__device__ __forceinline__ float ftanh(float x) {
    float e = __expf(2.f * x);
    return 1.f - __fdividef(2.f, e + 1.f);
}

__device__ __forceinline__ uint32_t bfbits(float v) {
    return (uint32_t)__bfloat16_as_ushort(__float2bfloat16(v));
}

// ---------------- scratch (device globals) ----------------------------------
__device__ float g_xg[(size_t)BT_ * N4U];             // [B*T, 4U]
// h in MMA-fragment-major order (recurrence)
__device__ __nv_bfloat16 g_hhiP[2][B_ * U_];
__device__ __nv_bfloat16 g_hloP[2][B_ * U_];
__device__ unsigned g_bar2[T_];                       // per-step barrier counters
// xgemm operands, fragment-major in gmem:
// A (x): [tile_m=BT/16][k16=32][lane=32][8 bf16 = regs 0..3 x elems 0..1]
__device__ __nv_bfloat16 g_xFhi[(size_t)BT_ * D_];
__device__ __nv_bfloat16 g_xFlo[(size_t)BT_ * D_];
// B (W^T): [n8=512][k16=32][lane=32][8 bf16 = bh0 bh1 bl0 bl1]
__device__ __nv_bfloat16 g_wF[(size_t)N4U * D_ * 2];

// ---------------- init -------------------------------------------------------
__global__ void lstm_init() {
    int i = blockIdx.x * blockDim.x + threadIdx.x;
    if (i < B_ * U_) {
        g_hhiP[0][i] = __float2bfloat16(0.f);
        g_hloP[0][i] = __float2bfloat16(0.f);
    }
    if (i < T_) g_bar2[i] = 0u;
}

// ---------------- split-precision converters (fragment-major output) ----------
// conv_x v2: gather form. One thread per output fragment row (8 bf16 = uint4).
// 4 coalesced float2 reads, 2 coalesced uint4 writes. Same layout/values as v1.
__global__ void conv_x(const float* __restrict__ x) {
    size_t idx = (size_t)blockIdx.x * blockDim.x + threadIdx.x;
    if (idx >= (size_t)(BT_ / 16) * 32 * 32) return;   // 2048*32*32 = 2.1M
    int lane = (int)(idx & 31);
    int k16 = (int)((idx >> 5) & 31);
    int tile_m = (int)(idx >> 10);

    int rr_low = lane >> 2;
    int kp = lane & 3;
    int bt0 = tile_m * 16 + rr_low;
    int bt1 = bt0 + 8;
    int k0 = k16 * 16 + 2 * kp;

    float2 v00 = *(const float2*)(x + (size_t)bt0 * D_ + k0);
    float2 v10 = *(const float2*)(x + (size_t)bt1 * D_ + k0);
    float2 v01 = *(const float2*)(x + (size_t)bt0 * D_ + k0 + 8);
    float2 v11 = *(const float2*)(x + (size_t)bt1 * D_ + k0 + 8);

    uint4 hi, lo;
    {
        uint32_t h0x = bfbits(v00.x), h0y = bfbits(v00.y);
        uint32_t h1x = bfbits(v10.x), h1y = bfbits(v10.y);
        uint32_t h2x = bfbits(v01.x), h2y = bfbits(v01.y);
        uint32_t h3x = bfbits(v11.x), h3y = bfbits(v11.y);
        hi.x = h0x | (h0y << 16);
        hi.y = h1x | (h1y << 16);
        hi.z = h2x | (h2y << 16);
        hi.w = h3x | (h3y << 16);
        lo.x = bfbits(v00.x - __bfloat162float(__ushort_as_bfloat16((unsigned short)h0x)))
             | (bfbits(v00.y - __bfloat162float(__ushort_as_bfloat16((unsigned short)h0y))) << 16);
        lo.y = bfbits(v10.x - __bfloat162float(__ushort_as_bfloat16((unsigned short)h1x)))
             | (bfbits(v10.y - __bfloat162float(__ushort_as_bfloat16((unsigned short)h1y))) << 16);
        lo.z = bfbits(v01.x - __bfloat162float(__ushort_as_bfloat16((unsigned short)h2x)))
             | (bfbits(v01.y - __bfloat162float(__ushort_as_bfloat16((unsigned short)h2y))) << 16);
        lo.w = bfbits(v11.x - __bfloat162float(__ushort_as_bfloat16((unsigned short)h3x)))
             | (bfbits(v11.y - __bfloat162float(__ushort_as_bfloat16((unsigned short)h3y))) << 16);
    }

    size_t base = (((size_t)tile_m * 32 + k16) * 32 + lane) * 8;
    *(uint4*)(g_xFhi + base) = hi;
    *(uint4*)(g_xFlo + base) = lo;
}
__global__ void conv_w(const float* __restrict__ W) {
    size_t i = (size_t)blockIdx.x * blockDim.x + threadIdx.x;  // over n*512+k
    if (i >= (size_t)N4U * D_) return;
    int n = (int)(i >> 9);
    int k = (int)(i & 511);
    float v = W[(size_t)k * N4U + n];
    __nv_bfloat16 hi = __float2bfloat16(v);
    __nv_bfloat16 lo = __float2bfloat16(v - __bfloat162float(hi));
    int n8 = n >> 3, k16 = k >> 4;
    int lane = (n & 7) * 4 + ((k >> 1) & 3);
    int reg = (k >> 3) & 1;
    int e = k & 1;
    size_t base = (((size_t)n8 * 32 + k16) * 32 + lane) * 8;
    g_wF[base + reg * 2 + e] = hi;
    g_wF[base + 4 + reg * 2 + e] = lo;
}

// ---------------- xgemm v3: smem-free fragment-major mma.sync, 512 thr ---------
// CTA 128x128, 16 warps (4m x 4n), warp tile 32x32, K=512 in 32 k16 steps.
// All operands LDG.128 fragment-major; double-buffered; no __syncthreads.
__global__ __launch_bounds__(512, 1)
void lstm_xgemm_mma() {
    const int tid = threadIdx.x;
    const int wid = tid >> 5;
    const int lane = tid & 31;
    const int wm = wid & 3;           // 0..3 (m32 tile)
    const int wn = wid >> 2;          // 0..3 (n32 tile)
    const int lq = lane >> 2;
    const int lr = (lane & 3) << 1;
    const int tm_base = blockIdx.y * 8 + wm * 2;    // tile_m of i=0 (2 tiles)
    const int n8_base = blockIdx.x * 16 + wn * 4;   // n8 of j=0 (4 tiles)

    float acc[2][4][4];
    #pragma unroll
    for (int i = 0; i < 2; i++)
        #pragma unroll
        for (int j = 0; j < 4; j++)
            #pragma unroll
            for (int q = 0; q < 4; q++) acc[i][j][q] = 0.f;

    uint4 Ah[2], Al[2], Bv[4];
    uint4 Ah_n[2], Al_n[2], Bv_n[4];

    // prime k16 = 0
    #pragma unroll
    for (int i = 0; i < 2; i++) {
        size_t off = (((size_t)(tm_base + i) * 32 + 0) * 32 + lane) * 8;
        Ah[i] = *(const uint4*)(g_xFhi + off);
        Al[i] = *(const uint4*)(g_xFlo + off);
    }
    #pragma unroll
    for (int j = 0; j < 4; j++) {
        size_t off = (((size_t)(n8_base + j) * 32 + 0) * 32 + lane) * 8;
        Bv[j] = *(const uint4*)(g_wF + off);
    }

    for (int k16 = 0; k16 < 32; k16++) {
        if (k16 < 31) {
            #pragma unroll
            for (int i = 0; i < 2; i++) {
                size_t off = (((size_t)(tm_base + i) * 32 + (k16 + 1)) * 32 + lane) * 8;
                Ah_n[i] = *(const uint4*)(g_xFhi + off);
                Al_n[i] = *(const uint4*)(g_xFlo + off);
            }
            #pragma unroll
            for (int j = 0; j < 4; j++) {
                size_t off = (((size_t)(n8_base + j) * 32 + (k16 + 1)) * 32 + lane) * 8;
                Bv_n[j] = *(const uint4*)(g_wF + off);
            }
        }
        #pragma unroll
        for (int i = 0; i < 2; i++) {
            const uint32_t* ahi = (const uint32_t*)&Ah[i];
            const uint32_t* alo = (const uint32_t*)&Al[i];
            #pragma unroll
            for (int j = 0; j < 4; j++) {
                uint32_t bh[2] = {Bv[j].x, Bv[j].y};
                uint32_t bl[2] = {Bv[j].z, Bv[j].w};
                MMA16816(acc[i][j], ahi, bh);
                MMA16816(acc[i][j], ahi, bl);
                MMA16816(acc[i][j], alo, bh);
            }
        }
        if (k16 < 31) {
            #pragma unroll
            for (int i = 0; i < 2; i++) { Ah[i] = Ah_n[i]; Al[i] = Al_n[i]; }
            #pragma unroll
            for (int j = 0; j < 4; j++) Bv[j] = Bv_n[j];
        }
    }

    const int m0 = blockIdx.y * 128;
    const int n0 = blockIdx.x * 128;
    #pragma unroll
    for (int i = 0; i < 2; i++) {
        int row = m0 + wm * 32 + i * 16 + lq;
        #pragma unroll
        for (int j = 0; j < 4; j++) {
            int col = n0 + wn * 32 + j * 8 + lr;
            *(float2*)&g_xg[(size_t)row * N4U + col] =
                make_float2(acc[i][j][0], acc[i][j][1]);
            *(float2*)&g_xg[(size_t)(row + 8) * N4U + col] =
                make_float2(acc[i][j][2], acc[i][j][3]);
        }
    }
}

// ---------------- grid-wide barrier (counter per step) --------------------------
__device__ __forceinline__ void gridbar2(int t) {
    __syncthreads();
    if (threadIdx.x == 0) {
        __threadfence();
        atomicAdd(&g_bar2[t], 1u);
        while (((volatile unsigned*)g_bar2)[t] < (unsigned)NB2) __nanosleep(32);
    }
    __syncthreads();
    __threadfence();
}

// ---------------- persistent recurrent LSTM (unchanged from R11/R14) ------------
__global__ __launch_bounds__(512)
void lstm_persist_mma(const float* __restrict__ W, float* __restrict__ out) {
    extern __shared__ char sm2[];
    __nv_bfloat16* Wp = (__nv_bfloat16*)sm2;         // 65536 bf16 = 128 KB
    float4* Zs4 = (float4*)(Wp + 65536);             // [4][576] float4 (b*9+u pad)

    const int tid = threadIdx.x;
    const int wid = tid >> 5;
    const int lane = tid & 31;
    const int wm = wid & 3;
    const int kq = wid >> 2;          // 0..3
    const int u0 = blockIdx.x * 8;
    const int lq = lane >> 2;
    const int lr = (lane & 3) << 1;

    // ---- load + split + permute W tile into smem (once): 32 cols x 1024 k ----
    for (int l = 0; l < 64; l++) {
        int idx = tid + l * 512;
        int cc = idx & 31;            // j = cc>>3 (gate), n = cc&7
        int k = idx >> 5;             // 0..1023
        int col = ((cc >> 3) << 10) + u0 + (cc & 7);
        float v = W[(size_t)k * N4U + col];
        __nv_bfloat16 hi = __float2bfloat16(v);
        __nv_bfloat16 lo = __float2bfloat16(v - __bfloat162float(hi));
        int kqi = k >> 8, si = (k >> 4) & 15, kk = k & 15;
        int j = cc >> 3, n = cc & 7;
        int ln = n * 4 + ((kk >> 1) & 3);
        int reg = kk >> 3, elem = kk & 1;
        int base = (((kqi * 16 + si) * 4 + j) * 32 + ln) * 8;
        Wp[base + reg * 2 + elem] = hi;
        Wp[base + 4 + reg * 2 + elem] = lo;
    }

    // ---- finisher cell: 1 per thread; precompute permuted h write addr ----
    const int fb = tid >> 3;          // batch 0..63
    const int fu = tid & 7;           // unit within tile
    const int ug = u0 + fu;           // global unit = h column
    const float* xgp = g_xg + (size_t)fb * T_ * N4U + ug;
    float c_reg = 0.f;
    int paddr;
    {
        int r = fb & 15, wmw = fb >> 4;
        int kqw = ug >> 8, sw = (ug >> 4) & 15, cw = ug & 15;
        int lnw = (r & 7) * 4 + ((cw >> 1) & 3);
        int regw = (r >> 3) | ((cw >> 3) << 1);
        paddr = (((kqw * 16 + sw) * 4 + wmw) * 256) + lnw * 8 + regw * 2 + (cw & 1);
    }

    float4* Zsl4 = Zs4 + kq * 576;
    const int ra = wm * 16 + lq;
    const int tbase = (kq * 16) * 4 + wm;   // tile id at s=0

    for (int t = 0; t < T_; t++) {
        // prefetch this step's x-gate values BEFORE the barrier (no h dependency)
        float xg0 = xgp[(size_t)t * N4U];
        float xg1 = xgp[(size_t)t * N4U + (1 << 10)];
        float xg2 = xgp[(size_t)t * N4U + (2 << 10)];
        float xg3 = xgp[(size_t)t * N4U + (3 << 10)];

        gridbar2(t);   // all h[t&1] writes visible; covers W-load at t=0

        const __nv_bfloat16* __restrict__ hh = g_hhiP[t & 1];
        const __nv_bfloat16* __restrict__ hl = g_hloP[t & 1];

        float acc[4][4];
        #pragma unroll
        for (int j = 0; j < 4; j++)
            #pragma unroll
            for (int q = 0; q < 4; q++) acc[j][q] = 0.f;

        // ---- software-pipelined mainloop: prefetch next s's h fragments ----
        const int off0 = tbase * 256 + lane * 8;
        uint4 Ah = *(const uint4*)(hh + off0);
        uint4 Al = *(const uint4*)(hl + off0);
        #pragma unroll
        for (int s = 0; s < 16; s++) {
            uint4 Ah_n, Al_n;
            if (s < 15) {
                const int offn = (tbase + (s + 1) * 4) * 256 + lane * 8;
                Ah_n = *(const uint4*)(hh + offn);
                Al_n = *(const uint4*)(hl + offn);
            }
            const uint32_t* ahi = (const uint32_t*)&Ah;
            const uint32_t* alo = (const uint32_t*)&Al;
            #pragma unroll
            for (int j = 0; j < 4; j++) {
                uint4 wv = *(const uint4*)(Wp + (((kq * 16 + s) * 4 + j) * 32 + lane) * 8);
                uint32_t bh[2] = {wv.x, wv.y};
                uint32_t bl[2] = {wv.z, wv.w};
                MMA16816(acc[j], ahi, bh);
                MMA16816(acc[j], ahi, bl);
                MMA16816(acc[j], alo, bh);
            }
            if (s < 15) { Ah = Ah_n; Al = Al_n; }
        }

        // ---- Zs slice write: gate-contiguous float4 per (b,u) ----
        Zsl4[ra * 9 + lr]           = make_float4(acc[0][0], acc[1][0], acc[2][0], acc[3][0]);
        Zsl4[ra * 9 + lr + 1]       = make_float4(acc[0][1], acc[1][1], acc[2][1], acc[3][1]);
        Zsl4[(ra + 8) * 9 + lr]     = make_float4(acc[0][2], acc[1][2], acc[2][2], acc[3][2]);
        Zsl4[(ra + 8) * 9 + lr + 1] = make_float4(acc[0][3], acc[1][3], acc[2][3], acc[3][3]);
        __syncthreads();

        // ---- finisher: 1 cell per thread; fixed-order kq sum (4 LDS.128) ----
        __nv_bfloat16* __restrict__ nhh = g_hhiP[(t + 1) & 1];
        __nv_bfloat16* __restrict__ nhl = g_hloP[(t + 1) & 1];
        {
            float z0 = xg0, z1 = xg1, z2 = xg2, z3 = xg3;
            #pragma unroll
            for (int p = 0; p < 4; p++) {
                float4 zp = Zs4[p * 576 + fb * 9 + fu];
                z0 += zp.x; z1 += zp.y; z2 += zp.z; z3 += zp.w;
            }
            float iv = fsigmoid(z0);
            float fv = fsigmoid(z1);
            float gv = ftanh(z2);
            float ov = fsigmoid(z3);
            c_reg = fv * c_reg + iv * gv;
            float hv = ov * ftanh(c_reg);
            __nv_bfloat16 hi = __float2bfloat16(hv);
            nhh[paddr] = hi;
            nhl[paddr] = __float2bfloat16(hv - __bfloat162float(hi));
            if (t == T_ - 1) out[fb * U_ + ug] = hv;
        }
        // next iteration's gridbar2 orders Zs reuse and h visibility
    }
}

// ---------------- launch --------------------------------------------------------
extern "C" void kernel_launch(void* const* d_in, const int* in_sizes, int n_in,
                              void* d_out, int out_size) {
    const float* x    = (const float*)d_in[0];
    const float* kern = (const float*)d_in[1];
    const float* rec  = (const float*)d_in[2];
    float* out = (float*)d_out;

    static int attr_done = 0;
    const size_t smem2 = (size_t)65536 * sizeof(__nv_bfloat16)
                       + (size_t)(4 * 576) * sizeof(float4);   // 128K + 36K = ~165 KB
    if (!attr_done) {
        cudaFuncSetAttribute(lstm_persist_mma,
                             cudaFuncAttributeMaxDynamicSharedMemorySize, (int)smem2);
        cudaFuncSetAttribute(lstm_persist_mma,
                             cudaFuncAttributePreferredSharedMemoryCarveout, 100);
        attr_done = 1;
    }

    lstm_init<<<(B_ * U_ + 255) / 256, 256>>>();

    conv_x<<<(int)(((size_t)(BT_ / 16) * 32 * 32 + 255) / 256), 256>>>(x);
    conv_w<<<(int)(((size_t)N4U * D_ + 255) / 256), 256>>>(kern);

    dim3 xg(N4U / 128, BT_ / 128);   // (32, 256)
    lstm_xgemm_mma<<<xg, 512>>>();

    lstm_persist_mma<<<NB2, 512, smem2>>>(rec, out);
}

// round 17
// speedup vs baseline: 1.2938x; 1.1917x over previous
#include <cuda_runtime.h>
#include <cuda_bf16.h>
#include <cuda_fp16.h>
#include <math.h>
#include <stdint.h>

typedef unsigned long long u64;

// Problem dims
#define B_ 64
#define T_ 512
#define D_ 512
#define U_ 1024
#define N4U 4096        // 4*U
#define BT_ (B_ * T_)   // 32768

#define NB2 128         // persistent blocks (1 per SM)

// mma.sync m16n8k16 fp16 (base PTX, works on compute_103) --------------------
#define MMA16816(c, a, b) \
    asm volatile("mma.sync.aligned.m16n8k16.row.col.f32.f16.f16.f32 " \
        "{%0,%1,%2,%3}, {%4,%5,%6,%7}, {%8,%9}, {%0,%1,%2,%3};" \
        : "+f"((c)[0]), "+f"((c)[1]), "+f"((c)[2]), "+f"((c)[3]) \
        : "r"((a)[0]), "r"((a)[1]), "r"((a)[2]), "r"((a)[3]), \
          "r"((b)[0]), "r"((b)[1]))

__device__ __forceinline__ float fsigmoid(float x) {
    return __fdividef(1.f, 1.f + __expf(-x));
}
__device__ __forceinline__ float ftanh(float x) {
    float e = __expf(2.f * x);
    return 1.f - __fdividef(2.f, e + 1.f);
}

__device__ __forceinline__ uint32_t hfbits(float v) {
    return (uint32_t)__half_as_ushort(__float2half(v));
}

// ---------------- scratch (device globals) ----------------------------------
__device__ float g_xg[(size_t)BT_ * N4U];             // [B*T, 4U]
// h single-fp16, MMA-fragment-major, double-buffered
__device__ __half g_hP[2][B_ * U_];
__device__ unsigned g_bar2[T_];                       // per-step barrier counters
// xgemm operands, fragment-major in gmem:
// A (x, single fp16): [tile_m=BT/16][k16=32][lane=32][8 f16]
__device__ __half g_xF[(size_t)BT_ * D_];
// B (Wx^T, fp16 hi+lo): [n8=512][k16=32][lane=32][8 = bh0 bh1 bl0 bl1]
__device__ __half g_wF[(size_t)N4U * D_ * 2];

// ---------------- init -------------------------------------------------------
__global__ void lstm_init() {
    int i = blockIdx.x * blockDim.x + threadIdx.x;
    if (i < B_ * U_) g_hP[0][i] = __float2half(0.f);
    if (i < T_) g_bar2[i] = 0u;
}

// ---------------- converters (fragment-major output) --------------------------
// conv_x: gather form, one thread per output fragment (8 f16 = uint4).
__global__ void conv_x(const float* __restrict__ x) {
    size_t idx = (size_t)blockIdx.x * blockDim.x + threadIdx.x;
    if (idx >= (size_t)(BT_ / 16) * 32 * 32) return;
    int lane = (int)(idx & 31);
    int k16 = (int)((idx >> 5) & 31);
    int tile_m = (int)(idx >> 10);

    int rr_low = lane >> 2;
    int kp = lane & 3;
    int bt0 = tile_m * 16 + rr_low;
    int bt1 = bt0 + 8;
    int k0 = k16 * 16 + 2 * kp;

    float2 v00 = *(const float2*)(x + (size_t)bt0 * D_ + k0);
    float2 v10 = *(const float2*)(x + (size_t)bt1 * D_ + k0);
    float2 v01 = *(const float2*)(x + (size_t)bt0 * D_ + k0 + 8);
    float2 v11 = *(const float2*)(x + (size_t)bt1 * D_ + k0 + 8);

    uint4 hi;
    hi.x = hfbits(v00.x) | (hfbits(v00.y) << 16);
    hi.y = hfbits(v10.x) | (hfbits(v10.y) << 16);
    hi.z = hfbits(v01.x) | (hfbits(v01.y) << 16);
    hi.w = hfbits(v11.x) | (hfbits(v11.y) << 16);

    size_t base = (((size_t)tile_m * 32 + k16) * 32 + lane) * 8;
    *(uint4*)(g_xF + base) = hi;
}
__global__ void conv_w(const float* __restrict__ W) {
    size_t i = (size_t)blockIdx.x * blockDim.x + threadIdx.x;  // over n*512+k
    if (i >= (size_t)N4U * D_) return;
    int n = (int)(i >> 9);
    int k = (int)(i & 511);
    float v = W[(size_t)k * N4U + n];
    __half hi = __float2half(v);
    __half lo = __float2half(v - __half2float(hi));
    int n8 = n >> 3, k16 = k >> 4;
    int lane = (n & 7) * 4 + ((k >> 1) & 3);
    int reg = (k >> 3) & 1;
    int e = k & 1;
    size_t base = (((size_t)n8 * 32 + k16) * 32 + lane) * 8;
    g_wF[base + reg * 2 + e] = hi;
    g_wF[base + 4 + reg * 2 + e] = lo;
}

// ---------------- xgemm: smem-free fragment-major mma.sync fp16, 512 thr -------
// CTA 128x128, 16 warps (4m x 4n), warp tile 32x32, K=512 in 32 k16 steps.
// A single fp16 (1 LDG.128/tile), B hi+lo packed (1 LDG.128/tile), 2 MMAs each.
__global__ __launch_bounds__(512, 1)
void lstm_xgemm_mma() {
    const int tid = threadIdx.x;
    const int wid = tid >> 5;
    const int lane = tid & 31;
    const int wm = wid & 3;           // 0..3 (m32 tile)
    const int wn = wid >> 2;          // 0..3 (n32 tile)
    const int lq = lane >> 2;
    const int lr = (lane & 3) << 1;
    const int tm_base = blockIdx.y * 8 + wm * 2;    // tile_m of i=0 (2 tiles)
    const int n8_base = blockIdx.x * 16 + wn * 4;   // n8 of j=0 (4 tiles)

    float acc[2][4][4];
    #pragma unroll
    for (int i = 0; i < 2; i++)
        #pragma unroll
        for (int j = 0; j < 4; j++)
            #pragma unroll
            for (int q = 0; q < 4; q++) acc[i][j][q] = 0.f;

    uint4 Ah[2], Bv[4];
    uint4 Ah_n[2], Bv_n[4];

    // prime k16 = 0
    #pragma unroll
    for (int i = 0; i < 2; i++) {
        size_t off = (((size_t)(tm_base + i) * 32 + 0) * 32 + lane) * 8;
        Ah[i] = *(const uint4*)(g_xF + off);
    }
    #pragma unroll
    for (int j = 0; j < 4; j++) {
        size_t off = (((size_t)(n8_base + j) * 32 + 0) * 32 + lane) * 8;
        Bv[j] = *(const uint4*)(g_wF + off);
    }

    for (int k16 = 0; k16 < 32; k16++) {
        if (k16 < 31) {
            #pragma unroll
            for (int i = 0; i < 2; i++) {
                size_t off = (((size_t)(tm_base + i) * 32 + (k16 + 1)) * 32 + lane) * 8;
                Ah_n[i] = *(const uint4*)(g_xF + off);
            }
            #pragma unroll
            for (int j = 0; j < 4; j++) {
                size_t off = (((size_t)(n8_base + j) * 32 + (k16 + 1)) * 32 + lane) * 8;
                Bv_n[j] = *(const uint4*)(g_wF + off);
            }
        }
        #pragma unroll
        for (int i = 0; i < 2; i++) {
            const uint32_t* ahi = (const uint32_t*)&Ah[i];
            #pragma unroll
            for (int j = 0; j < 4; j++) {
                uint32_t bh[2] = {Bv[j].x, Bv[j].y};
                uint32_t bl[2] = {Bv[j].z, Bv[j].w};
                MMA16816(acc[i][j], ahi, bh);
                MMA16816(acc[i][j], ahi, bl);
            }
        }
        if (k16 < 31) {
            #pragma unroll
            for (int i = 0; i < 2; i++) Ah[i] = Ah_n[i];
            #pragma unroll
            for (int j = 0; j < 4; j++) Bv[j] = Bv_n[j];
        }
    }

    const int m0 = blockIdx.y * 128;
    const int n0 = blockIdx.x * 128;
    #pragma unroll
    for (int i = 0; i < 2; i++) {
        int row = m0 + wm * 32 + i * 16 + lq;
        #pragma unroll
        for (int j = 0; j < 4; j++) {
            int col = n0 + wn * 32 + j * 8 + lr;
            *(float2*)&g_xg[(size_t)row * N4U + col] =
                make_float2(acc[i][j][0], acc[i][j][1]);
            *(float2*)&g_xg[(size_t)(row + 8) * N4U + col] =
                make_float2(acc[i][j][2], acc[i][j][3]);
        }
    }
}

// ---------------- grid-wide barrier (counter per step) --------------------------
__device__ __forceinline__ void gridbar2(int t) {
    __syncthreads();
    if (threadIdx.x == 0) {
        __threadfence();
        atomicAdd(&g_bar2[t], 1u);
        while (((volatile unsigned*)g_bar2)[t] < (unsigned)NB2) __nanosleep(32);
    }
    __syncthreads();
    __threadfence();
}

// ---------------- persistent recurrent LSTM (fp16, W 2-term, h 1-term) ----------
// 128 blocks x 512 thr. Block owns 8 units (32 z-cols), K=1024.
// Warps: wm = wid&3 (batch m16-tile), kq = wid>>2 (K-quarter of 256).
__global__ __launch_bounds__(512)
void lstm_persist_mma(const float* __restrict__ W, float* __restrict__ out) {
    extern __shared__ char sm2[];
    __half* Wp = (__half*)sm2;                       // 65536 f16 = 128 KB (hi+lo)
    float4* Zs4 = (float4*)(Wp + 65536);             // [4][576] float4 (b*9+u pad)

    const int tid = threadIdx.x;
    const int wid = tid >> 5;
    const int lane = tid & 31;
    const int wm = wid & 3;
    const int kq = wid >> 2;          // 0..3
    const int u0 = blockIdx.x * 8;
    const int lq = lane >> 2;
    const int lr = (lane & 3) << 1;

    // ---- load + split + permute Wrec tile into smem (once): 32 cols x 1024 k ----
    for (int l = 0; l < 64; l++) {
        int idx = tid + l * 512;
        int cc = idx & 31;            // j = cc>>3 (gate), n = cc&7
        int k = idx >> 5;             // 0..1023
        int col = ((cc >> 3) << 10) + u0 + (cc & 7);
        float v = W[(size_t)k * N4U + col];
        __half hi = __float2half(v);
        __half lo = __float2half(v - __half2float(hi));
        int kqi = k >> 8, si = (k >> 4) & 15, kk = k & 15;
        int j = cc >> 3, n = cc & 7;
        int ln = n * 4 + ((kk >> 1) & 3);
        int reg = kk >> 3, elem = kk & 1;
        int base = (((kqi * 16 + si) * 4 + j) * 32 + ln) * 8;
        Wp[base + reg * 2 + elem] = hi;
        Wp[base + 4 + reg * 2 + elem] = lo;
    }

    // ---- finisher cell: 1 per thread; precompute permuted h write addr ----
    const int fb = tid >> 3;          // batch 0..63
    const int fu = tid & 7;           // unit within tile
    const int ug = u0 + fu;           // global unit = h column
    const float* xgp = g_xg + (size_t)fb * T_ * N4U + ug;
    float c_reg = 0.f;
    int paddr;
    {
        int r = fb & 15, wmw = fb >> 4;
        int kqw = ug >> 8, sw = (ug >> 4) & 15, cw = ug & 15;
        int lnw = (r & 7) * 4 + ((cw >> 1) & 3);
        int regw = (r >> 3) | ((cw >> 3) << 1);
        paddr = (((kqw * 16 + sw) * 4 + wmw) * 256) + lnw * 8 + regw * 2 + (cw & 1);
    }

    float4* Zsl4 = Zs4 + kq * 576;
    const int ra = wm * 16 + lq;
    const int tbase = (kq * 16) * 4 + wm;   // tile id at s=0

    for (int t = 0; t < T_; t++) {
        // prefetch this step's x-gate values BEFORE the barrier (no h dependency)
        float xg0 = xgp[(size_t)t * N4U];
        float xg1 = xgp[(size_t)t * N4U + (1 << 10)];
        float xg2 = xgp[(size_t)t * N4U + (2 << 10)];
        float xg3 = xgp[(size_t)t * N4U + (3 << 10)];

        gridbar2(t);   // all h[t&1] writes visible; covers W-load at t=0

        const __half* __restrict__ hh = g_hP[t & 1];

        float acc[4][4];
        #pragma unroll
        for (int j = 0; j < 4; j++)
            #pragma unroll
            for (int q = 0; q < 4; q++) acc[j][q] = 0.f;

        // ---- software-pipelined mainloop: prefetch next s's h fragment ----
        const int off0 = tbase * 256 + lane * 8;
        uint4 Ah = *(const uint4*)(hh + off0);
        #pragma unroll
        for (int s = 0; s < 16; s++) {
            uint4 Ah_n;
            if (s < 15) {
                const int offn = (tbase + (s + 1) * 4) * 256 + lane * 8;
                Ah_n = *(const uint4*)(hh + offn);
            }
            const uint32_t* ahi = (const uint32_t*)&Ah;
            #pragma unroll
            for (int j = 0; j < 4; j++) {
                uint4 wv = *(const uint4*)(Wp + (((kq * 16 + s) * 4 + j) * 32 + lane) * 8);
                uint32_t bh[2] = {wv.x, wv.y};
                uint32_t bl[2] = {wv.z, wv.w};
                MMA16816(acc[j], ahi, bh);
                MMA16816(acc[j], ahi, bl);
            }
            if (s < 15) Ah = Ah_n;
        }

        // ---- Zs slice write: gate-contiguous float4 per (b,u) ----
        Zsl4[ra * 9 + lr]           = make_float4(acc[0][0], acc[1][0], acc[2][0], acc[3][0]);
        Zsl4[ra * 9 + lr + 1]       = make_float4(acc[0][1], acc[1][1], acc[2][1], acc[3][1]);
        Zsl4[(ra + 8) * 9 + lr]     = make_float4(acc[0][2], acc[1][2], acc[2][2], acc[3][2]);
        Zsl4[(ra + 8) * 9 + lr + 1] = make_float4(acc[0][3], acc[1][3], acc[2][3], acc[3][3]);
        __syncthreads();

        // ---- finisher: 1 cell per thread; fixed-order kq sum (4 LDS.128) ----
        __half* __restrict__ nhh = g_hP[(t + 1) & 1];
        {
            float z0 = xg0, z1 = xg1, z2 = xg2, z3 = xg3;
            #pragma unroll
            for (int p = 0; p < 4; p++) {
                float4 zp = Zs4[p * 576 + fb * 9 + fu];
                z0 += zp.x; z1 += zp.y; z2 += zp.z; z3 += zp.w;
            }
            float iv = fsigmoid(z0);
            float fv = fsigmoid(z1);
            float gv = ftanh(z2);
            float ov = fsigmoid(z3);
            c_reg = fv * c_reg + iv * gv;
            float hv = ov * ftanh(c_reg);
            nhh[paddr] = __float2half(hv);
            if (t == T_ - 1) out[fb * U_ + ug] = hv;
        }
        // next iteration's gridbar2 orders Zs reuse and h visibility
    }
}

// ---------------- launch --------------------------------------------------------
extern "C" void kernel_launch(void* const* d_in, const int* in_sizes, int n_in,
                              void* d_out, int out_size) {
    const float* x    = (const float*)d_in[0];
    const float* kern = (const float*)d_in[1];
    const float* rec  = (const float*)d_in[2];
    float* out = (float*)d_out;

    static int attr_done = 0;
    const size_t smem2 = (size_t)65536 * sizeof(__half)
                       + (size_t)(4 * 576) * sizeof(float4);   // 128K + 36K = ~164 KB
    if (!attr_done) {
        cudaFuncSetAttribute(lstm_persist_mma,
                             cudaFuncAttributeMaxDynamicSharedMemorySize, (int)smem2);
        cudaFuncSetAttribute(lstm_persist_mma,
                             cudaFuncAttributePreferredSharedMemoryCarveout, 100);
        attr_done = 1;
    }

    lstm_init<<<(B_ * U_ + 255) / 256, 256>>>();

    conv_x<<<(int)(((size_t)(BT_ / 16) * 32 * 32 + 255) / 256), 256>>>(x);
    conv_w<<<(int)(((size_t)N4U * D_ + 255) / 256), 256>>>(kern);

    dim3 xg(N4U / 128, BT_ / 128);   // (32, 256)
    lstm_xgemm_mma<<<xg, 512>>>();

    lstm_persist_mma<<<NB2, 512, smem2>>>(rec, out);
}